// round 7
// baseline (speedup 1.0000x reference)
#include <cuda_runtime.h>
#include <math.h>
#include <math_constants.h>

// TopLoss: three 8M x 2 fp32 diagrams.
//   l = dgm[:,0] - dgm[:,1], non-finite -> 0
//   top1 = max(l0); t01 = 1 - top1^2; t0 = sumsq(l0) - top1^2
//   t1 = sumsq(l1); t2 = sumsq(l2); loss = t01 + t0 + t1 + t2
// Output: (loss, t01, t0, t1, t2) as 5 fp32.
//
// Single fused kernel. Main loop: 13 full strides (unrolled x2, 6 LDG.128
// batched per iteration for MLP) + 1 predicated remainder. Last-CTA finalize.

#define NPAIRS   (8 * 1024 * 1024)
#define NVEC     (NPAIRS / 2)          // 4194304 float4 per array
#define NBLK     1184                  // 148 SMs, one resident wave
#define NTHR     256
#define STRIDE   (NBLK * NTHR)         // 303104
#define NFULL    13                    // NVEC / STRIDE
#define NREM     (NVEC - NFULL * STRIDE)  // 253952

// Per-block partials: {sumsq0, sumsq1, sumsq2, max_l0}
__device__ float4       g_partial[NBLK];
__device__ unsigned int g_count = 0;

__device__ __forceinline__ float bar_len(float a, float b) {
    float l = a - b;
    return isfinite(l) ? l : 0.0f;
}

__device__ __forceinline__ void acc_sum(const float4& v, float& s) {
    float la = bar_len(v.x, v.y);
    float lb = bar_len(v.z, v.w);
    s = fmaf(la, la, s);
    s = fmaf(lb, lb, s);
}

__device__ __forceinline__ void acc_sum_max(const float4& v, float& s, float& m) {
    float la = bar_len(v.x, v.y);
    float lb = bar_len(v.z, v.w);
    s = fmaf(la, la, s);
    s = fmaf(lb, lb, s);
    m = fmaxf(m, fmaxf(la, lb));
}

__device__ __forceinline__ void warp_reduce4(float& s0, float& s1, float& s2, float& m) {
    #pragma unroll
    for (int o = 16; o > 0; o >>= 1) {
        s0 += __shfl_down_sync(0xFFFFFFFFu, s0, o);
        s1 += __shfl_down_sync(0xFFFFFFFFu, s1, o);
        s2 += __shfl_down_sync(0xFFFFFFFFu, s2, o);
        m   = fmaxf(m, __shfl_down_sync(0xFFFFFFFFu, m, o));
    }
}

__global__ void __launch_bounds__(NTHR)
toploss_fused(const float4* __restrict__ d0,
              const float4* __restrict__ d1,
              const float4* __restrict__ d2,
              float* __restrict__ out) {
    const int base = blockIdx.x * NTHR + threadIdx.x;

    float s0 = 0.0f, s1 = 0.0f, s2 = 0.0f;
    float m = -CUDART_INF_F;

    // ---- 6 double-iterations: 6 independent LDG.128 batched per step ----
    #pragma unroll
    for (int j = 0; j < NFULL / 2; j++) {
        int ia = base + (2 * j)     * STRIDE;
        int ib = base + (2 * j + 1) * STRIDE;
        float4 a0 = __ldcs(d0 + ia);
        float4 a1 = __ldcs(d1 + ia);
        float4 a2 = __ldcs(d2 + ia);
        float4 b0 = __ldcs(d0 + ib);
        float4 b1 = __ldcs(d1 + ib);
        float4 b2 = __ldcs(d2 + ib);
        acc_sum_max(a0, s0, m);
        acc_sum(a1, s1);
        acc_sum(a2, s2);
        acc_sum_max(b0, s0, m);
        acc_sum(b1, s1);
        acc_sum(b2, s2);
    }

    // ---- 13th full stride ----
    {
        int i = base + (NFULL - 1) * STRIDE;
        float4 a0 = __ldcs(d0 + i);
        float4 a1 = __ldcs(d1 + i);
        float4 a2 = __ldcs(d2 + i);
        acc_sum_max(a0, s0, m);
        acc_sum(a1, s1);
        acc_sum(a2, s2);
    }

    // ---- predicated remainder ----
    if (base < NREM) {
        int i = base + NFULL * STRIDE;
        float4 a0 = __ldcs(d0 + i);
        float4 a1 = __ldcs(d1 + i);
        float4 a2 = __ldcs(d2 + i);
        acc_sum_max(a0, s0, m);
        acc_sum(a1, s1);
        acc_sum(a2, s2);
    }

    // ---- intra-block reduce ----
    warp_reduce4(s0, s1, s2, m);

    __shared__ float sh0[NTHR / 32], sh1[NTHR / 32], sh2[NTHR / 32], shm[NTHR / 32];
    int lane = threadIdx.x & 31;
    int warp = threadIdx.x >> 5;
    if (lane == 0) { sh0[warp] = s0; sh1[warp] = s1; sh2[warp] = s2; shm[warp] = m; }
    __syncthreads();

    if (warp == 0) {
        const int nw = NTHR / 32;
        s0 = (lane < nw) ? sh0[lane] : 0.0f;
        s1 = (lane < nw) ? sh1[lane] : 0.0f;
        s2 = (lane < nw) ? sh2[lane] : 0.0f;
        m  = (lane < nw) ? shm[lane] : -CUDART_INF_F;
        #pragma unroll
        for (int o = 4; o > 0; o >>= 1) {   // nw == 8
            s0 += __shfl_down_sync(0xFFFFFFFFu, s0, o);
            s1 += __shfl_down_sync(0xFFFFFFFFu, s1, o);
            s2 += __shfl_down_sync(0xFFFFFFFFu, s2, o);
            m   = fmaxf(m, __shfl_down_sync(0xFFFFFFFFu, m, o));
        }
        if (lane == 0) {
            g_partial[blockIdx.x] = make_float4(s0, s1, s2, m);
            __threadfence();  // release: partial visible before counter bump
        }
    }
    __syncthreads();

    // ---- last-CTA finalize ----
    __shared__ unsigned int s_ticket;
    if (threadIdx.x == 0) s_ticket = atomicAdd(&g_count, 1u);
    __syncthreads();
    if (s_ticket != NBLK - 1) return;

    s0 = 0.0f; s1 = 0.0f; s2 = 0.0f; m = -CUDART_INF_F;
    for (int i = threadIdx.x; i < NBLK; i += NTHR) {
        float4 p = g_partial[i];
        s0 += p.x; s1 += p.y; s2 += p.z;
        m = fmaxf(m, p.w);
    }

    warp_reduce4(s0, s1, s2, m);

    if (lane == 0) { sh0[warp] = s0; sh1[warp] = s1; sh2[warp] = s2; shm[warp] = m; }
    __syncthreads();

    if (warp == 0) {
        const int nw = NTHR / 32;
        s0 = (lane < nw) ? sh0[lane] : 0.0f;
        s1 = (lane < nw) ? sh1[lane] : 0.0f;
        s2 = (lane < nw) ? sh2[lane] : 0.0f;
        m  = (lane < nw) ? shm[lane] : -CUDART_INF_F;
        #pragma unroll
        for (int o = 4; o > 0; o >>= 1) {
            s0 += __shfl_down_sync(0xFFFFFFFFu, s0, o);
            s1 += __shfl_down_sync(0xFFFFFFFFu, s1, o);
            s2 += __shfl_down_sync(0xFFFFFFFFu, s2, o);
            m   = fmaxf(m, __shfl_down_sync(0xFFFFFFFFu, m, o));
        }
        if (lane == 0) {
            float m2  = m * m;
            float t01 = 1.0f - m2;
            float t0  = s0 - m2;
            out[0] = t01 + t0 + s1 + s2;  // loss
            out[1] = t01;
            out[2] = t0;
            out[3] = s1;
            out[4] = s2;
            g_count = 0;                  // reset for next graph replay
        }
    }
}

extern "C" void kernel_launch(void* const* d_in, const int* in_sizes, int n_in,
                              void* d_out, int out_size) {
    const float4* d0 = (const float4*)d_in[0];
    const float4* d1 = (const float4*)d_in[1];
    const float4* d2 = (const float4*)d_in[2];
    toploss_fused<<<NBLK, NTHR>>>(d0, d1, d2, (float*)d_out);
}

// round 8
// speedup vs baseline: 1.1181x; 1.1181x over previous
#include <cuda_runtime.h>
#include <math.h>
#include <math_constants.h>

// TopLoss: three 8M x 2 fp32 diagrams.
//   l = dgm[:,0] - dgm[:,1], non-finite -> 0
//   top1 = max(l0); t01 = 1 - top1^2; t0 = sumsq(l0) - top1^2
//   t1 = sumsq(l1); t2 = sumsq(l2); loss = t01 + t0 + t1 + t2
// Output: (loss, t01, t0, t1, t2) as 5 fp32.
//
// Single fused kernel, occupancy-first (regs capped via launch_bounds -> 64
// warps/SM). 512-thread blocks quarter the CTA count vs R3 (592 vs 1184),
// shrinking the last-CTA atomic tail while keeping the identical load pattern.

#define NPAIRS   (8 * 1024 * 1024)
#define NVEC     (NPAIRS / 2)          // 4194304 float4 per array
#define NTHR     512
#define NBLK     592                   // 148 SMs * 4 CTAs, one resident wave
#define STRIDE   (NBLK * NTHR)         // 303104 (identical to R3 best run)
#define NWARP    (NTHR / 32)           // 16

// Per-block partials: {sumsq0, sumsq1, sumsq2, max_l0}
__device__ float4       g_partial[NBLK];
__device__ unsigned int g_count = 0;

__device__ __forceinline__ float bar_len(float a, float b) {
    float l = a - b;
    return isfinite(l) ? l : 0.0f;
}

__device__ __forceinline__ void warp_reduce4(float& s0, float& s1, float& s2, float& m) {
    #pragma unroll
    for (int o = 16; o > 0; o >>= 1) {
        s0 += __shfl_down_sync(0xFFFFFFFFu, s0, o);
        s1 += __shfl_down_sync(0xFFFFFFFFu, s1, o);
        s2 += __shfl_down_sync(0xFFFFFFFFu, s2, o);
        m   = fmaxf(m, __shfl_down_sync(0xFFFFFFFFu, m, o));
    }
}

__global__ void __launch_bounds__(NTHR, 4)
toploss_fused(const float4* __restrict__ d0,
              const float4* __restrict__ d1,
              const float4* __restrict__ d2,
              float* __restrict__ out) {
    float s0 = 0.0f, s1 = 0.0f, s2 = 0.0f;
    float m = -CUDART_INF_F;

    for (int i = blockIdx.x * NTHR + threadIdx.x; i < NVEC; i += STRIDE) {
        // issue all three loads up front, then compute
        float4 v0 = d0[i];
        float4 v1 = d1[i];
        float4 v2 = d2[i];

        float la = bar_len(v0.x, v0.y);
        float lb = bar_len(v0.z, v0.w);
        s0 = fmaf(la, la, s0);
        s0 = fmaf(lb, lb, s0);
        m  = fmaxf(m, fmaxf(la, lb));

        la = bar_len(v1.x, v1.y);
        lb = bar_len(v1.z, v1.w);
        s1 = fmaf(la, la, s1);
        s1 = fmaf(lb, lb, s1);

        la = bar_len(v2.x, v2.y);
        lb = bar_len(v2.z, v2.w);
        s2 = fmaf(la, la, s2);
        s2 = fmaf(lb, lb, s2);
    }

    // ---- intra-block reduce ----
    warp_reduce4(s0, s1, s2, m);

    __shared__ float sh0[NWARP], sh1[NWARP], sh2[NWARP], shm[NWARP];
    int lane = threadIdx.x & 31;
    int warp = threadIdx.x >> 5;
    if (lane == 0) { sh0[warp] = s0; sh1[warp] = s1; sh2[warp] = s2; shm[warp] = m; }
    __syncthreads();

    if (warp == 0) {
        s0 = (lane < NWARP) ? sh0[lane] : 0.0f;
        s1 = (lane < NWARP) ? sh1[lane] : 0.0f;
        s2 = (lane < NWARP) ? sh2[lane] : 0.0f;
        m  = (lane < NWARP) ? shm[lane] : -CUDART_INF_F;
        #pragma unroll
        for (int o = 8; o > 0; o >>= 1) {   // NWARP == 16
            s0 += __shfl_down_sync(0xFFFFFFFFu, s0, o);
            s1 += __shfl_down_sync(0xFFFFFFFFu, s1, o);
            s2 += __shfl_down_sync(0xFFFFFFFFu, s2, o);
            m   = fmaxf(m, __shfl_down_sync(0xFFFFFFFFu, m, o));
        }
        if (lane == 0) {
            g_partial[blockIdx.x] = make_float4(s0, s1, s2, m);
            __threadfence();  // release: partial visible before counter bump
        }
    }
    __syncthreads();

    // ---- last-CTA finalize ----
    __shared__ unsigned int s_ticket;
    if (threadIdx.x == 0) s_ticket = atomicAdd(&g_count, 1u);
    __syncthreads();
    if (s_ticket != NBLK - 1) return;

    s0 = 0.0f; s1 = 0.0f; s2 = 0.0f; m = -CUDART_INF_F;
    for (int i = threadIdx.x; i < NBLK; i += NTHR) {
        float4 p = g_partial[i];
        s0 += p.x; s1 += p.y; s2 += p.z;
        m = fmaxf(m, p.w);
    }

    warp_reduce4(s0, s1, s2, m);

    if (lane == 0) { sh0[warp] = s0; sh1[warp] = s1; sh2[warp] = s2; shm[warp] = m; }
    __syncthreads();

    if (warp == 0) {
        s0 = (lane < NWARP) ? sh0[lane] : 0.0f;
        s1 = (lane < NWARP) ? sh1[lane] : 0.0f;
        s2 = (lane < NWARP) ? sh2[lane] : 0.0f;
        m  = (lane < NWARP) ? shm[lane] : -CUDART_INF_F;
        #pragma unroll
        for (int o = 8; o > 0; o >>= 1) {
            s0 += __shfl_down_sync(0xFFFFFFFFu, s0, o);
            s1 += __shfl_down_sync(0xFFFFFFFFu, s1, o);
            s2 += __shfl_down_sync(0xFFFFFFFFu, s2, o);
            m   = fmaxf(m, __shfl_down_sync(0xFFFFFFFFu, m, o));
        }
        if (lane == 0) {
            float m2  = m * m;
            float t01 = 1.0f - m2;
            float t0  = s0 - m2;
            out[0] = t01 + t0 + s1 + s2;  // loss
            out[1] = t01;
            out[2] = t0;
            out[3] = s1;
            out[4] = s2;
            g_count = 0;                  // reset for next graph replay
        }
    }
}

extern "C" void kernel_launch(void* const* d_in, const int* in_sizes, int n_in,
                              void* d_out, int out_size) {
    const float4* d0 = (const float4*)d_in[0];
    const float4* d1 = (const float4*)d_in[1];
    const float4* d2 = (const float4*)d_in[2];
    toploss_fused<<<NBLK, NTHR>>>(d0, d1, d2, (float*)d_out);
}